// round 14
// baseline (speedup 1.0000x reference)
#include <cuda_runtime.h>
#include <math.h>

// FFF: fast-feedforward conditional tree MLP.
// B=8192, D_in=D_out=2048, depth 11 -> 12 routing steps, 4095 nodes.
//
// Pipeline (all capture-legal, event fork/join):
//   stream0: route(c0) route(c1) route(c2) route(c3)
//   s2:      transpose  out(c0)  out(c1)  out(c2)  out(c3)
// out(c) waits on route(c); route(c+1) is independent of out(c), so route and
// out chunks co-reside on the SMs: out's latency-immune streaming fills the
// L1 slots route's serial chains leave idle.

#define DEPTH    11
#define NSTEPS   (DEPTH + 1)
#define N_NODES  4095
#define DDIM     2048
#define D4       (DDIM / 4)     // 512 float4 per row
#define BATCH    8192
#define RT       64             // route block size
#define NCHUNK   4
#define CHUNK    (BATCH / NCHUNK)

__device__ float g_WoutT[(size_t)N_NODES * DDIM];
__device__ int   g_nodes[(size_t)BATCH * NSTEPS];
__device__ float g_gval [(size_t)BATCH * NSTEPS];

// 64x64 tile transpose, 256 threads, coalesced both sides.
__global__ __launch_bounds__(256) void transpose_wout(const float* __restrict__ Wout) {
    __shared__ float tile[64][65];
    const int n0 = blockIdx.x * 64;
    const int o0 = blockIdx.y * 64;
    const int tid = threadIdx.x;

    #pragma unroll
    for (int k = 0; k < 16; ++k) {
        int e = k * 256 + tid;
        int ol = e >> 6;
        int nl = e & 63;
        int n = n0 + nl;
        float v = 0.f;
        if (n < N_NODES)
            v = Wout[(size_t)(o0 + ol) * N_NODES + n];
        tile[nl][ol] = v;
    }
    __syncthreads();

    #pragma unroll
    for (int k = 0; k < 16; ++k) {
        int e = k * 256 + tid;
        int nl = e >> 6;
        int ol = e & 63;
        int n = n0 + nl;
        if (n < N_NODES)
            g_WoutT[(size_t)n * DDIM + (o0 + ol)] = tile[nl][ol];
    }
}

__device__ __forceinline__ float dot4(float4 a, float4 b) {
    return fmaf(a.x, b.x, fmaf(a.y, b.y, fmaf(a.z, b.z, a.w * b.w)));
}

__device__ __forceinline__ void fma4(float4& a, float g, float4 v) {
    a.x = fmaf(g, v.x, a.x);
    a.y = fmaf(g, v.y, a.y);
    a.z = fmaf(g, v.z, a.z);
    a.w = fmaf(g, v.w, a.w);
}

__device__ __forceinline__ float gelu_exact(float s) {
    return 0.5f * s * (1.0f + erff(s * 0.70710678118654752f));
}

// 64 threads per block, one sample per block.
__global__ __launch_bounds__(RT, 12) void route_kernel(
    const float* __restrict__ x,
    const float* __restrict__ Win,
    int base)
{
    const int b    = base + blockIdx.x;
    const int tid  = threadIdx.x;
    const int lane = tid & 31;
    const int warp = tid >> 5;

    const float4* __restrict__ Win4 = reinterpret_cast<const float4*>(Win);
    const float4* __restrict__ x4   = reinterpret_cast<const float4*>(x) + (size_t)b * D4;

    float4 xr[8];
    #pragma unroll
    for (int i = 0; i < 8; ++i)
        xr[i] = x4[tid + RT * i];

    __shared__ float red[2][2];

    int node = 0;
    #pragma unroll
    for (int d = 0; d < NSTEPS; ++d) {
        const float4* __restrict__ wr = Win4 + (size_t)node * D4;

        float p0 = 0.f, p1 = 0.f;
        #pragma unroll
        for (int i = 0; i < 8; i += 2) {
            p0 += dot4(wr[tid + RT * i],       xr[i]);
            p1 += dot4(wr[tid + RT * (i + 1)], xr[i + 1]);
        }
        float p = p0 + p1;

        // XOR butterfly: all lanes converge to a bit-identical warp sum.
        #pragma unroll
        for (int off = 16; off > 0; off >>= 1)
            p += __shfl_xor_sync(0xffffffffu, p, off);

        if (lane == 0) red[d & 1][warp] = p;
        __syncthreads();

        float score = red[d & 1][0] + red[d & 1][1];

        if (tid == 0) {
            g_nodes[(size_t)b * NSTEPS + d] = node;
            g_gval [(size_t)b * NSTEPS + d] = gelu_exact(score);
        }

        node = node * 2 + 1 + (score >= 0.0f ? 1 : 0);
    }
}

// Output accumulation: fully parallel, 12 independent row gathers per sample.
__global__ __launch_bounds__(128, 8) void out_kernel(
    float* __restrict__ out,
    int base)
{
    const int b   = base + blockIdx.x;
    const int tid = threadIdx.x;

    const float4* __restrict__ Wt4 = reinterpret_cast<const float4*>(g_WoutT);

    int   nd[NSTEPS];
    float gg[NSTEPS];
    #pragma unroll
    for (int d = 0; d < NSTEPS; ++d) {
        nd[d] = g_nodes[(size_t)b * NSTEPS + d];
        gg[d] = g_gval [(size_t)b * NSTEPS + d];
    }

    float4 a0 = make_float4(0.f, 0.f, 0.f, 0.f);
    float4 a1 = make_float4(0.f, 0.f, 0.f, 0.f);
    float4 a2 = make_float4(0.f, 0.f, 0.f, 0.f);
    float4 a3 = make_float4(0.f, 0.f, 0.f, 0.f);

    #pragma unroll
    for (int d = 0; d < NSTEPS; ++d) {
        const float4* __restrict__ vr = Wt4 + (size_t)nd[d] * D4;
        float g = gg[d];
        fma4(a0, g, vr[tid]);
        fma4(a1, g, vr[tid + 128]);
        fma4(a2, g, vr[tid + 256]);
        fma4(a3, g, vr[tid + 384]);
    }

    float4* __restrict__ o4 = reinterpret_cast<float4*>(out) + (size_t)b * D4;
    o4[tid]       = a0;
    o4[tid + 128] = a1;
    o4[tid + 256] = a2;
    o4[tid + 384] = a3;
}

extern "C" void kernel_launch(void* const* d_in, const int* in_sizes, int n_in,
                              void* d_out, int out_size)
{
    const float* x    = (const float*)d_in[0];   // (8192, 2048)
    const float* Win  = (const float*)d_in[1];   // (4095, 2048)
    const float* Wout = (const float*)d_in[2];   // (2048, 4095)
    float* out = (float*)d_out;                  // (8192, 2048)

    cudaStream_t s2;
    cudaStreamCreateWithFlags(&s2, cudaStreamNonBlocking);
    cudaEvent_t eFork, eJoin, eR[NCHUNK];
    cudaEventCreateWithFlags(&eFork, cudaEventDisableTiming);
    cudaEventCreateWithFlags(&eJoin, cudaEventDisableTiming);
    for (int c = 0; c < NCHUNK; ++c)
        cudaEventCreateWithFlags(&eR[c], cudaEventDisableTiming);

    // Fork side stream; transpose runs there, overlapping route(0).
    cudaEventRecord(eFork, 0);
    cudaStreamWaitEvent(s2, eFork, 0);
    dim3 tg((N_NODES + 63) / 64, DDIM / 64);
    transpose_wout<<<tg, 256, 0, s2>>>(Wout);

    // Chunked route -> out pipeline.
    for (int c = 0; c < NCHUNK; ++c) {
        route_kernel<<<CHUNK, RT>>>(x, Win, c * CHUNK);
        cudaEventRecord(eR[c], 0);
        cudaStreamWaitEvent(s2, eR[c], 0);
        out_kernel<<<CHUNK, 128, 0, s2>>>(out, c * CHUNK);
    }

    // Join: main stream waits for the last out chunk.
    cudaEventRecord(eJoin, s2);
    cudaStreamWaitEvent(0, eJoin, 0);
}

// round 15
// speedup vs baseline: 1.0387x; 1.0387x over previous
#include <cuda_runtime.h>
#include <math.h>

// FFF: fast-feedforward conditional tree MLP.
// B=8192, D_in=D_out=2048, depth 11 -> 12 routing steps, 4095 nodes.
//
// Wave-aligned pipeline (route wave = 148 SMs x 12 blocks = 1776):
//   s0: route(3552) route(3552) route(1088)
//   s2: transpose   out(3552)   out(3552)  out(1088)
// out(c) gates on route(c) via events; out chunks hide under later route
// chunks. Kernels identical to the best-measured versions.

#define DEPTH    11
#define NSTEPS   (DEPTH + 1)
#define N_NODES  4095
#define DDIM     2048
#define D4       (DDIM / 4)     // 512 float4 per row
#define BATCH    8192
#define RT       64             // route block size

#define C0       3552           // 2 route waves
#define C1       3552           // 2 route waves
#define C2       (BATCH - C0 - C1)  // 1088 tail

__device__ float g_WoutT[(size_t)N_NODES * DDIM];
__device__ int   g_nodes[(size_t)BATCH * NSTEPS];
__device__ float g_gval [(size_t)BATCH * NSTEPS];

// 64x64 tile transpose, 256 threads, coalesced both sides.
__global__ __launch_bounds__(256) void transpose_wout(const float* __restrict__ Wout) {
    __shared__ float tile[64][65];
    const int n0 = blockIdx.x * 64;
    const int o0 = blockIdx.y * 64;
    const int tid = threadIdx.x;

    #pragma unroll
    for (int k = 0; k < 16; ++k) {
        int e = k * 256 + tid;
        int ol = e >> 6;
        int nl = e & 63;
        int n = n0 + nl;
        float v = 0.f;
        if (n < N_NODES)
            v = Wout[(size_t)(o0 + ol) * N_NODES + n];
        tile[nl][ol] = v;
    }
    __syncthreads();

    #pragma unroll
    for (int k = 0; k < 16; ++k) {
        int e = k * 256 + tid;
        int nl = e >> 6;
        int ol = e & 63;
        int n = n0 + nl;
        if (n < N_NODES)
            g_WoutT[(size_t)n * DDIM + (o0 + ol)] = tile[nl][ol];
    }
}

__device__ __forceinline__ float dot4(float4 a, float4 b) {
    return fmaf(a.x, b.x, fmaf(a.y, b.y, fmaf(a.z, b.z, a.w * b.w)));
}

__device__ __forceinline__ void fma4(float4& a, float g, float4 v) {
    a.x = fmaf(g, v.x, a.x);
    a.y = fmaf(g, v.y, a.y);
    a.z = fmaf(g, v.z, a.z);
    a.w = fmaf(g, v.w, a.w);
}

__device__ __forceinline__ float gelu_exact(float s) {
    return 0.5f * s * (1.0f + erff(s * 0.70710678118654752f));
}

// 64 threads per block, one sample per block, 12 blocks/SM.
__global__ __launch_bounds__(RT, 12) void route_kernel(
    const float* __restrict__ x,
    const float* __restrict__ Win,
    int base)
{
    const int b    = base + blockIdx.x;
    const int tid  = threadIdx.x;
    const int lane = tid & 31;
    const int warp = tid >> 5;

    const float4* __restrict__ Win4 = reinterpret_cast<const float4*>(Win);
    const float4* __restrict__ x4   = reinterpret_cast<const float4*>(x) + (size_t)b * D4;

    float4 xr[8];
    #pragma unroll
    for (int i = 0; i < 8; ++i)
        xr[i] = x4[tid + RT * i];

    __shared__ float red[2][2];

    int node = 0;
    #pragma unroll
    for (int d = 0; d < NSTEPS; ++d) {
        const float4* __restrict__ wr = Win4 + (size_t)node * D4;

        float p0 = 0.f, p1 = 0.f;
        #pragma unroll
        for (int i = 0; i < 8; i += 2) {
            p0 += dot4(wr[tid + RT * i],       xr[i]);
            p1 += dot4(wr[tid + RT * (i + 1)], xr[i + 1]);
        }
        float p = p0 + p1;

        // XOR butterfly: all lanes converge to a bit-identical warp sum.
        #pragma unroll
        for (int off = 16; off > 0; off >>= 1)
            p += __shfl_xor_sync(0xffffffffu, p, off);

        if (lane == 0) red[d & 1][warp] = p;
        __syncthreads();

        float score = red[d & 1][0] + red[d & 1][1];

        if (tid == 0) {
            g_nodes[(size_t)b * NSTEPS + d] = node;
            g_gval [(size_t)b * NSTEPS + d] = gelu_exact(score);
        }

        node = node * 2 + 1 + (score >= 0.0f ? 1 : 0);
    }
}

// Output accumulation: fully parallel, 12 independent row gathers per sample.
__global__ __launch_bounds__(128, 8) void out_kernel(
    float* __restrict__ out,
    int base)
{
    const int b   = base + blockIdx.x;
    const int tid = threadIdx.x;

    const float4* __restrict__ Wt4 = reinterpret_cast<const float4*>(g_WoutT);

    int   nd[NSTEPS];
    float gg[NSTEPS];
    #pragma unroll
    for (int d = 0; d < NSTEPS; ++d) {
        nd[d] = g_nodes[(size_t)b * NSTEPS + d];
        gg[d] = g_gval [(size_t)b * NSTEPS + d];
    }

    float4 a0 = make_float4(0.f, 0.f, 0.f, 0.f);
    float4 a1 = make_float4(0.f, 0.f, 0.f, 0.f);
    float4 a2 = make_float4(0.f, 0.f, 0.f, 0.f);
    float4 a3 = make_float4(0.f, 0.f, 0.f, 0.f);

    #pragma unroll
    for (int d = 0; d < NSTEPS; ++d) {
        const float4* __restrict__ vr = Wt4 + (size_t)nd[d] * D4;
        float g = gg[d];
        fma4(a0, g, vr[tid]);
        fma4(a1, g, vr[tid + 128]);
        fma4(a2, g, vr[tid + 256]);
        fma4(a3, g, vr[tid + 384]);
    }

    float4* __restrict__ o4 = reinterpret_cast<float4*>(out) + (size_t)b * D4;
    o4[tid]       = a0;
    o4[tid + 128] = a1;
    o4[tid + 256] = a2;
    o4[tid + 384] = a3;
}

extern "C" void kernel_launch(void* const* d_in, const int* in_sizes, int n_in,
                              void* d_out, int out_size)
{
    const float* x    = (const float*)d_in[0];   // (8192, 2048)
    const float* Win  = (const float*)d_in[1];   // (4095, 2048)
    const float* Wout = (const float*)d_in[2];   // (2048, 4095)
    float* out = (float*)d_out;                  // (8192, 2048)

    cudaStream_t s2;
    cudaStreamCreateWithFlags(&s2, cudaStreamNonBlocking);
    cudaEvent_t eFork, eJoin, eR0, eR1, eR2;
    cudaEventCreateWithFlags(&eFork, cudaEventDisableTiming);
    cudaEventCreateWithFlags(&eJoin, cudaEventDisableTiming);
    cudaEventCreateWithFlags(&eR0, cudaEventDisableTiming);
    cudaEventCreateWithFlags(&eR1, cudaEventDisableTiming);
    cudaEventCreateWithFlags(&eR2, cudaEventDisableTiming);

    // Fork side stream; transpose runs there, overlapping route(c0).
    cudaEventRecord(eFork, 0);
    cudaStreamWaitEvent(s2, eFork, 0);
    dim3 tg((N_NODES + 63) / 64, DDIM / 64);
    transpose_wout<<<tg, 256, 0, s2>>>(Wout);

    // Wave-aligned route chunks on s0; out chunks trail on s2.
    route_kernel<<<C0, RT>>>(x, Win, 0);
    cudaEventRecord(eR0, 0);
    route_kernel<<<C1, RT>>>(x, Win, C0);
    cudaEventRecord(eR1, 0);
    route_kernel<<<C2, RT>>>(x, Win, C0 + C1);
    cudaEventRecord(eR2, 0);

    cudaStreamWaitEvent(s2, eR0, 0);
    out_kernel<<<C0, 128, 0, s2>>>(out, 0);
    cudaStreamWaitEvent(s2, eR1, 0);
    out_kernel<<<C1, 128, 0, s2>>>(out, C0);
    cudaStreamWaitEvent(s2, eR2, 0);
    out_kernel<<<C2, 128, 0, s2>>>(out, C0 + C1);

    // Join: main stream waits for the last out chunk.
    cudaEventRecord(eJoin, s2);
    cudaStreamWaitEvent(0, eJoin, 0);
}